// round 5
// baseline (speedup 1.0000x reference)
#include <cuda_runtime.h>
#include <cstdint>

typedef unsigned long long ull;

#define NB 128
#define NT 4096
#define NTH 1024
// quarter-plane: 2048 slots * 16B + 32B pad  (stride ≡ 32 mod 128 → conflict-free)
#define QPLANE 32800u
#define SMEM_DYN (4u * QPLANE)

__device__ __forceinline__ float ex2f_(float x) {
    float y; asm("ex2.approx.f32 %0, %1;" : "=f"(y) : "f"(x)); return y;
}
__device__ __forceinline__ float rcpf_(float x) {
    float y; asm("rcp.approx.f32 %0, %1;" : "=f"(y) : "f"(x)); return y;
}
__device__ __forceinline__ float tanhf_(float x) {
    float y; asm("tanh.approx.f32 %0, %1;" : "=f"(y) : "f"(x)); return y;
}
__device__ __forceinline__ void pfma(ull& d, ull a, ull b) {
    asm("fma.rn.f32x2 %0, %1, %2, %0;" : "+l"(d) : "l"(a), "l"(b));
}
__device__ __forceinline__ ull pack2(float a, float b) {
    ull p; asm("mov.b64 %0, {%1, %2};" : "=l"(p) : "f"(a), "f"(b)); return p;
}
__device__ __forceinline__ float2 unpack2(ull p) {
    float2 r; asm("mov.b64 {%0, %1}, %2;" : "=f"(r.x), "=f"(r.y) : "l"(p)); return r;
}
__device__ __forceinline__ uint32_t s2u(const void* p) {
    uint32_t a;
    asm("{ .reg .u64 t; cvta.to.shared.u64 t, %1; cvt.u32.u64 %0, t; }"
        : "=r"(a) : "l"(p));
    return a;
}
__device__ __forceinline__ void cp16(uint32_t dst, const void* g) {
    asm volatile("cp.async.cg.shared.global [%0], [%1], 16;" :: "r"(dst), "l"(g));
}
__device__ __forceinline__ void cpcommit() {
    asm volatile("cp.async.commit_group;");
}
template <int N>
__device__ __forceinline__ void cpwait() {
    asm volatile("cp.async.wait_group %0;" :: "n"(N));
}

__global__ void __launch_bounds__(NTH, 1)
additive_attn_fused(const float* __restrict__ query,   // [B,1,16]
                    const float* __restrict__ key,     // [B,T,16]
                    const float* __restrict__ value,   // [B,T,16]
                    const float* __restrict__ W1,      // [32,16]
                    const float* __restrict__ W2,      // [32,16]
                    const float* __restrict__ bias,    // scalar
                    const float* __restrict__ v_w,     // [1,32]
                    const float* __restrict__ v_b,     // [1]
                    float* __restrict__ out_ctx,       // [B,16]
                    float* __restrict__ out_attn)      // [B,T]
{
    extern __shared__ __align__(16) char dsm[];   // 4 quarter-planes
    const uint32_t sb = s2u(dsm);

    const int b    = blockIdx.x;
    const int tid  = threadIdx.x;
    const int lane = tid & 31;
    const int wid  = tid >> 5;

    __shared__ ull        sW2p[32 * 8];   // W2 rows as packed f32x2 pairs
    __shared__ ulonglong2 scv[32];        // .x = (qproj_w + bias, 0), .y lo = v_w[w]
    __shared__ float      sred[32 * 17];
    __shared__ float      sbc[18];        // [0]=max, [1]=sum, [2..17]=ctx

    // ---- G0: stage key pass 0 (tokens 0..2047) ----
    {
        const float* kbase = key + (size_t)b * NT * 16;
        #pragma unroll
        for (int k = 0; k < 8; k++) {
            const int c  = tid + k * NTH;     // chunk 0..8191
            const int tc = c >> 2;            // token 0..2047
            const int q  = c & 3;
            cp16(sb + q * QPLANE + tc * 16, kbase + (size_t)c * 4);
        }
        cpcommit();
    }

    // ---- weight staging + q projection ----
    if (tid < 128) {
        float4 wr = reinterpret_cast<const float4*>(W2)[tid];
        sW2p[tid * 2 + 0] = pack2(wr.x, wr.y);
        sW2p[tid * 2 + 1] = pack2(wr.z, wr.w);
    }
    if (tid >= 160 && tid < 192) {
        const int w = tid - 160;
        float acc = *bias;
        #pragma unroll
        for (int d = 0; d < 16; d++)
            acc = fmaf(query[b * 16 + d], W1[w * 16 + d], acc);
        scv[w].x = pack2(acc, 0.0f);
        scv[w].y = pack2(v_w[w], 0.0f);
    }

    const float vb = *v_b;
    float s[4];

    // ================= Phase A =================
    #pragma unroll
    for (int pass = 0; pass < 2; pass++) {
        cpwait<0>();
        __syncthreads();     // staged keys + (pass0) weights visible to all

        // read this thread's 2 tokens from conflict-free planes
        ull ka[8], kb[8];
        #pragma unroll
        for (int q = 0; q < 4; q++) {
            ulonglong2 va = *reinterpret_cast<const ulonglong2*>(
                dsm + q * QPLANE + (size_t)tid * 16);
            ka[2 * q] = va.x; ka[2 * q + 1] = va.y;
            ulonglong2 vb_ = *reinterpret_cast<const ulonglong2*>(
                dsm + q * QPLANE + (size_t)(tid + 1024) * 16);
            kb[2 * q] = vb_.x; kb[2 * q + 1] = vb_.y;
        }
        __syncthreads();     // all reads done before buffer reuse

        // prefetch next tile: pass1 keys (G1) or value tile0 (G2)
        if (pass == 0) {
            const float* kbase = key + ((size_t)b * NT + 2048) * 16;
            #pragma unroll
            for (int k = 0; k < 8; k++) {
                const int c  = tid + k * NTH;
                const int tc = c >> 2;
                const int q  = c & 3;
                cp16(sb + q * QPLANE + tc * 16, kbase + (size_t)c * 4);
            }
            cpcommit();
        } else {
            const float* vbase = value + (size_t)b * NT * 16;   // tile 0 -> half 0
            #pragma unroll
            for (int k = 0; k < 4; k++) {
                const int c  = tid + k * NTH;     // chunk 0..4095
                const int tc = c >> 2;            // token 0..1023
                const int q  = c & 3;
                cp16(sb + q * QPLANE + tc * 16, vbase + (size_t)c * 4);
            }
            cpcommit();
        }

        float a0 = vb, a1 = vb;
        #pragma unroll 4
        for (int w = 0; w < 32; w++) {
            const ulonglong2 cc = scv[w];
            ull acc0 = cc.x;
            ull acc1 = cc.x;
            const float vw = unpack2(cc.y).x;
            const ulonglong2* wr =
                reinterpret_cast<const ulonglong2*>(&sW2p[w * 8]);
            ulonglong2 wv = wr[0];
            pfma(acc0, ka[0], wv.x); pfma(acc1, kb[0], wv.x);
            pfma(acc0, ka[1], wv.y); pfma(acc1, kb[1], wv.y);
            wv = wr[1];
            pfma(acc0, ka[2], wv.x); pfma(acc1, kb[2], wv.x);
            pfma(acc0, ka[3], wv.y); pfma(acc1, kb[3], wv.y);
            wv = wr[2];
            pfma(acc0, ka[4], wv.x); pfma(acc1, kb[4], wv.x);
            pfma(acc0, ka[5], wv.y); pfma(acc1, kb[5], wv.y);
            wv = wr[3];
            pfma(acc0, ka[6], wv.x); pfma(acc1, kb[6], wv.x);
            pfma(acc0, ka[7], wv.y); pfma(acc1, kb[7], wv.y);

            const float2 h0 = unpack2(acc0);
            const float2 h1 = unpack2(acc1);
            const float t0h = tanhf_(h0.x + h0.y);
            const float t1h = tanhf_(h1.x + h1.y);
            a0 = fmaf(vw, t0h, a0);
            a1 = fmaf(vw, t1h, a1);
        }
        s[2 * pass + 0] = a0;   // token tid + (2*pass)  *1024
        s[2 * pass + 1] = a1;   // token tid + (2*pass+1)*1024
    }

    // ================= Block max =================
    float m = fmaxf(fmaxf(s[0], s[1]), fmaxf(s[2], s[3]));
    #pragma unroll
    for (int o = 16; o > 0; o >>= 1)
        m = fmaxf(m, __shfl_xor_sync(0xffffffffu, m, o));
    if (lane == 0) sred[wid] = m;
    __syncthreads();
    if (wid == 0) {
        float mm = sred[lane];
        #pragma unroll
        for (int o = 16; o > 0; o >>= 1)
            mm = fmaxf(mm, __shfl_xor_sync(0xffffffffu, mm, o));
        if (lane == 0) sbc[0] = mm;
    }

    // prefetch value tile 1 (half 1) while reduction settles — G3
    {
        const float* vbase = value + ((size_t)b * NT + 1024) * 16;
        #pragma unroll
        for (int k = 0; k < 4; k++) {
            const int c  = tid + k * NTH;
            const int tc = c >> 2;
            const int q  = c & 3;
            cp16(sb + q * QPLANE + (1024 + tc) * 16, vbase + (size_t)c * 4);
        }
        cpcommit();
    }
    __syncthreads();
    const float L = 1.4426950408889634f;
    const float negmL = -sbc[0] * L;

    // ================= Phase B (ping-pong value tiles) =================
    float e_[4];
    float csum = 0.0f;
    ull cv[8];
    #pragma unroll
    for (int i = 0; i < 8; i++) cv[i] = 0ull;

    #pragma unroll
    for (int j = 0; j < 4; j++) {
        // tile j's group must be complete. For j<3 one newer group may stay
        // in flight; at j==3 it is the ONLY pending group, so wait for all.
        if (j < 3) cpwait<1>(); else cpwait<0>();
        __syncthreads();

        const float e = ex2f_(fmaf(s[j], L, negmL));
        e_[j] = e;
        csum += e;
        const ull ee = pack2(e, e);
        const int slot = tid + (j & 1) * 1024;
        #pragma unroll
        for (int q = 0; q < 4; q++) {
            ulonglong2 vv = *reinterpret_cast<const ulonglong2*>(
                dsm + q * QPLANE + (size_t)slot * 16);
            pfma(cv[2 * q],     ee, vv.x);
            pfma(cv[2 * q + 1], ee, vv.y);
        }

        if (j < 2) {
            __syncthreads();   // all reads of this half done before overwrite
            // prefetch tile j+2 into the same half
            const float* vbase = value + ((size_t)b * NT + (j + 2) * 1024) * 16;
            #pragma unroll
            for (int k = 0; k < 4; k++) {
                const int c  = tid + k * NTH;
                const int tc = c >> 2;
                const int q  = c & 3;
                cp16(sb + q * QPLANE + ((j & 1) * 1024 + tc) * 16,
                     vbase + (size_t)c * 4);
            }
            cpcommit();
        }
    }

    // unpack ctx accumulators to 16 scalars
    float cvf[16];
    #pragma unroll
    for (int i = 0; i < 8; i++) {
        float2 u = unpack2(cv[i]);
        cvf[2 * i] = u.x; cvf[2 * i + 1] = u.y;
    }

    // ================= Deterministic 17-value reduction =================
    #pragma unroll
    for (int o = 16; o > 0; o >>= 1) {
        csum += __shfl_xor_sync(0xffffffffu, csum, o);
        #pragma unroll
        for (int i = 0; i < 16; i++)
            cvf[i] += __shfl_xor_sync(0xffffffffu, cvf[i], o);
    }
    if (lane == 0) {
        sred[wid * 17] = csum;
        #pragma unroll
        for (int i = 0; i < 16; i++) sred[wid * 17 + 1 + i] = cvf[i];
    }
    __syncthreads();
    if (tid < 17) {
        float a = sred[tid];
        #pragma unroll
        for (int w = 1; w < 32; w++) a += sred[w * 17 + tid];
        sbc[1 + tid] = a;
    }
    __syncthreads();

    const float inv = rcpf_(sbc[1]);

    #pragma unroll
    for (int j = 0; j < 4; j++)
        out_attn[(size_t)b * NT + tid + j * NTH] = e_[j] * inv;

    if (tid >= 1 && tid < 17)
        out_ctx[b * 16 + (tid - 1)] = sbc[1 + tid] * inv;
}

extern "C" void kernel_launch(void* const* d_in, const int* in_sizes, int n_in,
                              void* d_out, int out_size) {
    const float* query = (const float*)d_in[0];
    const float* key   = (const float*)d_in[1];
    const float* value = (const float*)d_in[2];
    const float* W1    = (const float*)d_in[3];
    const float* W2    = (const float*)d_in[4];
    const float* bias  = (const float*)d_in[5];
    const float* v_w   = (const float*)d_in[6];
    const float* v_b   = (const float*)d_in[7];

    float* out_ctx  = (float*)d_out;            // [B,1,16]
    float* out_attn = (float*)d_out + NB * 16;  // [B,T]

    cudaFuncSetAttribute(additive_attn_fused,
                         cudaFuncAttributeMaxDynamicSharedMemorySize, SMEM_DYN);

    additive_attn_fused<<<NB, NTH, SMEM_DYN>>>(query, key, value, W1, W2,
                                               bias, v_w, v_b, out_ctx, out_attn);
}

// round 6
// speedup vs baseline: 1.2718x; 1.2718x over previous
#include <cuda_runtime.h>
#include <cstdint>

typedef unsigned long long ull;

#define NB 128
#define NT 4096
#define K1_NTH 256
#define NCHUNK 4            // CTAs per batch
#define TOKC 1024           // tokens per CTA

__device__ float g_scratch[NB * NCHUNK * 18];   // [cta][lmax, sum, ctx16]

__device__ __forceinline__ float ex2f_(float x) {
    float y; asm("ex2.approx.f32 %0, %1;" : "=f"(y) : "f"(x)); return y;
}
__device__ __forceinline__ float rcpf_(float x) {
    float y; asm("rcp.approx.f32 %0, %1;" : "=f"(y) : "f"(x)); return y;
}
__device__ __forceinline__ float tanhf_(float x) {
    float y; asm("tanh.approx.f32 %0, %1;" : "=f"(y) : "f"(x)); return y;
}
__device__ __forceinline__ void pfma(ull& d, ull a, ull b) {
    asm("fma.rn.f32x2 %0, %1, %2, %0;" : "+l"(d) : "l"(a), "l"(b));
}
__device__ __forceinline__ ull pack2(float a, float b) {
    ull p; asm("mov.b64 %0, {%1, %2};" : "=l"(p) : "f"(a), "f"(b)); return p;
}
__device__ __forceinline__ float2 unpack2(ull p) {
    float2 r; asm("mov.b64 {%0, %1}, %2;" : "=f"(r.x), "=f"(r.y) : "l"(p)); return r;
}

// ================== K1: partial softmax over 1024 tokens ==================
__global__ void __launch_bounds__(K1_NTH, 4)
attn_partial(const float* __restrict__ query,   // [B,1,16]
             const float* __restrict__ key,     // [B,T,16]
             const float* __restrict__ value,   // [B,T,16]
             const float* __restrict__ W1,      // [32,16]
             const float* __restrict__ W2,      // [32,16]
             const float* __restrict__ bias,    // scalar
             const float* __restrict__ v_w,     // [1,32]
             const float* __restrict__ v_b,     // [1]
             float* __restrict__ out_attn)      // [B,T] (unnormalized e)
{
    const int cta   = blockIdx.x;
    const int b     = cta >> 2;
    const int base  = (cta & 3) * TOKC;
    const int tid   = threadIdx.x;
    const int lane  = tid & 31;
    const int wid   = tid >> 5;

    __shared__ ull        sW2p[32 * 8];
    __shared__ ulonglong2 scv[32];        // .x = (qproj_w + bias, 0), .y lo = v_w[w]
    __shared__ float      sred[8 * 17];
    __shared__ float      sbc[1];         // local max broadcast

    if (tid < 128) {
        float4 wr = reinterpret_cast<const float4*>(W2)[tid];
        sW2p[tid * 2 + 0] = pack2(wr.x, wr.y);
        sW2p[tid * 2 + 1] = pack2(wr.z, wr.w);
    }
    if (tid >= 128 && tid < 160) {
        const int w = tid - 128;
        float acc = *bias;
        #pragma unroll
        for (int d = 0; d < 16; d++)
            acc = fmaf(query[b * 16 + d], W1[w * 16 + d], acc);
        scv[w].x = pack2(acc, 0.0f);
        scv[w].y = pack2(v_w[w], 0.0f);
    }
    __syncthreads();

    const float vb = *v_b;

    // ---------- Phase A: scores for 4 tokens (2 per pass) ----------
    float s[4];
    #pragma unroll
    for (int jp = 0; jp < 2; jp++) {
        const int t0 = base + tid + (2 * jp + 0) * K1_NTH;
        const int t1 = base + tid + (2 * jp + 1) * K1_NTH;
        const ulonglong2* kp0 =
            reinterpret_cast<const ulonglong2*>(key + ((size_t)b * NT + t0) * 16);
        const ulonglong2* kp1 =
            reinterpret_cast<const ulonglong2*>(key + ((size_t)b * NT + t1) * 16);
        ull ka[8], kb[8];
        #pragma unroll
        for (int i = 0; i < 4; i++) {
            ulonglong2 va = kp0[i]; ka[2*i] = va.x; ka[2*i+1] = va.y;
            ulonglong2 vb_ = kp1[i]; kb[2*i] = vb_.x; kb[2*i+1] = vb_.y;
        }

        float a0 = vb, a1 = vb;
        #pragma unroll 4
        for (int w = 0; w < 32; w++) {
            const ulonglong2 cc = scv[w];
            ull acc0 = cc.x;
            ull acc1 = cc.x;
            const float vw = unpack2(cc.y).x;
            const ulonglong2* wr =
                reinterpret_cast<const ulonglong2*>(&sW2p[w * 8]);
            ulonglong2 wv = wr[0];
            pfma(acc0, ka[0], wv.x); pfma(acc1, kb[0], wv.x);
            pfma(acc0, ka[1], wv.y); pfma(acc1, kb[1], wv.y);
            wv = wr[1];
            pfma(acc0, ka[2], wv.x); pfma(acc1, kb[2], wv.x);
            pfma(acc0, ka[3], wv.y); pfma(acc1, kb[3], wv.y);
            wv = wr[2];
            pfma(acc0, ka[4], wv.x); pfma(acc1, kb[4], wv.x);
            pfma(acc0, ka[5], wv.y); pfma(acc1, kb[5], wv.y);
            wv = wr[3];
            pfma(acc0, ka[6], wv.x); pfma(acc1, kb[6], wv.x);
            pfma(acc0, ka[7], wv.y); pfma(acc1, kb[7], wv.y);

            const float2 h0 = unpack2(acc0);
            const float2 h1 = unpack2(acc1);
            const float t0h = tanhf_(h0.x + h0.y);
            const float t1h = tanhf_(h1.x + h1.y);
            a0 = fmaf(vw, t0h, a0);
            a1 = fmaf(vw, t1h, a1);
        }
        s[2 * jp + 0] = a0;
        s[2 * jp + 1] = a1;
    }

    // ---------- CTA-local max (8 warps) ----------
    float m = fmaxf(fmaxf(s[0], s[1]), fmaxf(s[2], s[3]));
    #pragma unroll
    for (int o = 16; o > 0; o >>= 1)
        m = fmaxf(m, __shfl_xor_sync(0xffffffffu, m, o));
    if (lane == 0) sred[wid] = m;
    __syncthreads();
    if (wid == 0) {
        float mm = (lane < 8) ? sred[lane] : -3.4e38f;
        #pragma unroll
        for (int o = 16; o > 0; o >>= 1)
            mm = fmaxf(mm, __shfl_xor_sync(0xffffffffu, mm, o));
        if (lane == 0) sbc[0] = mm;
    }
    __syncthreads();
    const float lmax  = sbc[0];
    const float L     = 1.4426950408889634f;
    const float negmL = -lmax * L;

    // ---------- Phase B: e + weighted value accumulation ----------
    float csum = 0.0f;
    ull cv[8];
    #pragma unroll
    for (int i = 0; i < 8; i++) cv[i] = 0ull;

    #pragma unroll
    for (int j = 0; j < 4; j++) {
        const int t = base + tid + j * K1_NTH;
        const float e = ex2f_(fmaf(s[j], L, negmL));
        csum += e;
        out_attn[(size_t)b * NT + t] = e;       // unnormalized; K2 rescales
        const ull ee = pack2(e, e);
        const ulonglong2* vp =
            reinterpret_cast<const ulonglong2*>(value + ((size_t)b * NT + t) * 16);
        #pragma unroll
        for (int i = 0; i < 4; i++) {
            ulonglong2 vv = vp[i];
            pfma(cv[2*i],   ee, vv.x);
            pfma(cv[2*i+1], ee, vv.y);
        }
    }

    float cvf[16];
    #pragma unroll
    for (int i = 0; i < 8; i++) {
        float2 u = unpack2(cv[i]);
        cvf[2*i] = u.x; cvf[2*i+1] = u.y;
    }

    // ---------- Deterministic 17-value reduction over 8 warps ----------
    #pragma unroll
    for (int o = 16; o > 0; o >>= 1) {
        csum += __shfl_xor_sync(0xffffffffu, csum, o);
        #pragma unroll
        for (int i = 0; i < 16; i++)
            cvf[i] += __shfl_xor_sync(0xffffffffu, cvf[i], o);
    }
    if (lane == 0) {
        sred[wid * 17] = csum;
        #pragma unroll
        for (int i = 0; i < 16; i++) sred[wid * 17 + 1 + i] = cvf[i];
    }
    __syncthreads();
    if (tid < 17) {
        float a = sred[tid];
        #pragma unroll
        for (int w = 1; w < 8; w++) a += sred[w * 17 + tid];
        g_scratch[cta * 18 + 1 + tid] = a;      // sum, ctx[16]
    }
    if (tid == 17) g_scratch[cta * 18] = lmax;
}

// ================== K2: combine 4 partials + rescale ==================
__global__ void __launch_bounds__(256)
attn_combine(float* __restrict__ out_ctx,       // [B,16]
             float* __restrict__ out_attn)      // [B,T]
{
    const int b   = blockIdx.x;
    const int tid = threadIdx.x;

    __shared__ float sp[NCHUNK * 18];
    if (tid < NCHUNK * 18) sp[tid] = g_scratch[b * NCHUNK * 18 + tid];
    __syncthreads();

    const float L = 1.4426950408889634f;
    const float l0 = sp[0], l1 = sp[18], l2 = sp[36], l3 = sp[54];
    const float gmax = fmaxf(fmaxf(l0, l1), fmaxf(l2, l3));
    const float c0 = ex2f_((l0 - gmax) * L);
    const float c1 = ex2f_((l1 - gmax) * L);
    const float c2 = ex2f_((l2 - gmax) * L);
    const float c3 = ex2f_((l3 - gmax) * L);
    const float total = sp[1]*c0 + sp[19]*c1 + sp[37]*c2 + sp[55]*c3;
    const float inv = rcpf_(total);

    if (tid < 16)
        out_ctx[b * 16 + tid] =
            (sp[2+tid]*c0 + sp[20+tid]*c1 + sp[38+tid]*c2 + sp[56+tid]*c3) * inv;

    const float f[4] = {c0 * inv, c1 * inv, c2 * inv, c3 * inv};
    float4* ap = reinterpret_cast<float4*>(out_attn + (size_t)b * NT);
    #pragma unroll
    for (int j = 0; j < 4; j++) {
        const int idx = tid + j * 256;      // float4 index 0..1023
        const float sc = f[idx >> 8];       // 256 float4 per 1024-token chunk
        float4 v = ap[idx];
        v.x *= sc; v.y *= sc; v.z *= sc; v.w *= sc;
        ap[idx] = v;
    }
}

extern "C" void kernel_launch(void* const* d_in, const int* in_sizes, int n_in,
                              void* d_out, int out_size) {
    const float* query = (const float*)d_in[0];
    const float* key   = (const float*)d_in[1];
    const float* value = (const float*)d_in[2];
    const float* W1    = (const float*)d_in[3];
    const float* W2    = (const float*)d_in[4];
    const float* bias  = (const float*)d_in[5];
    const float* v_w   = (const float*)d_in[6];
    const float* v_b   = (const float*)d_in[7];

    float* out_ctx  = (float*)d_out;            // [B,1,16]
    float* out_attn = (float*)d_out + NB * 16;  // [B,T]

    attn_partial<<<NB * NCHUNK, K1_NTH>>>(query, key, value, W1, W2,
                                          bias, v_w, v_b, out_attn);
    attn_combine<<<NB, 256>>>(out_ctx, out_attn);
}